// round 7
// baseline (speedup 1.0000x reference)
#include <cuda_runtime.h>

// out[n, i] = b[n, i] * sum_j a[n, j],  B = L = 8192, fp32.
// R1 fused shape, but TWO rows per CTA: one barrier + reduce per 2 rows
// (96KB -> 192KB of traffic per sync). Same total loads in flight per thread.

constexpr int L = 8192;
constexpr int THREADS = 256;
constexpr int NWARPS = THREADS / 32;               // 8
constexpr int VECS_PER_ROW = L / 4;                // 2048 float4
constexpr int VPR = VECS_PER_ROW / THREADS;        // 8 vec-slots per row
constexpr int HALF = VPR / 2;                      // 4 per row in phase loops

__global__ __launch_bounds__(THREADS, 8)
void outer_product_rowscale2(const float* __restrict__ a,
                             const float* __restrict__ b,
                             float* __restrict__ out)
{
    __shared__ float ws0[NWARPS];
    __shared__ float ws1[NWARPS];

    const int tid  = threadIdx.x;
    const size_t r0 = (size_t)(2 * blockIdx.x)     * VECS_PER_ROW;
    const size_t r1 = (size_t)(2 * blockIdx.x + 1) * VECS_PER_ROW;

    const float4* a4 = reinterpret_cast<const float4*>(a);
    const float4* b4 = reinterpret_cast<const float4*>(b);
    float4* o4       = reinterpret_cast<float4*>(out);

    // ---- Phase 1: row-sums of both rows (8 loads/thread total) ----
    float s0 = 0.f, s1 = 0.f;      // row 0 accumulators
    float t0 = 0.f, t1 = 0.f;      // row 1 accumulators
    #pragma unroll
    for (int i = 0; i < VPR; i++) {
        float4 v = __ldcs(&a4[r0 + tid + i * THREADS]);
        s0 += (v.x + v.y); s1 += (v.z + v.w);
    }
    #pragma unroll
    for (int i = 0; i < VPR; i++) {
        float4 v = __ldcs(&a4[r1 + tid + i * THREADS]);
        t0 += (v.x + v.y); t1 += (v.z + v.w);
    }
    float s = s0 + s1;
    float t = t0 + t1;

    #pragma unroll
    for (int off = 16; off > 0; off >>= 1) {
        s += __shfl_xor_sync(0xFFFFFFFFu, s, off);
        t += __shfl_xor_sync(0xFFFFFFFFu, t, off);
    }

    if ((tid & 31) == 0) { ws0[tid >> 5] = s; ws1[tid >> 5] = t; }
    __syncthreads();                                // the ONLY barrier

    const float4 u0 = *reinterpret_cast<const float4*>(&ws0[0]);
    const float4 u1 = *reinterpret_cast<const float4*>(&ws0[4]);
    const float scale0 = ((u0.x + u0.y) + (u0.z + u0.w))
                       + ((u1.x + u1.y) + (u1.z + u1.w));
    const float4 q0 = *reinterpret_cast<const float4*>(&ws1[0]);
    const float4 q1 = *reinterpret_cast<const float4*>(&ws1[4]);
    const float scale1 = ((q0.x + q0.y) + (q0.z + q0.w))
                       + ((q1.x + q1.y) + (q1.z + q1.w));

    // ---- Phase 2: stream both rows, interleaved for issue density ----
    #pragma unroll
    for (int i = 0; i < VPR; i++) {
        float4 v = __ldcs(&b4[r0 + tid + i * THREADS]);
        v.x *= scale0; v.y *= scale0; v.z *= scale0; v.w *= scale0;
        __stcs(&o4[r0 + tid + i * THREADS], v);
        float4 w = __ldcs(&b4[r1 + tid + i * THREADS]);
        w.x *= scale1; w.y *= scale1; w.z *= scale1; w.w *= scale1;
        __stcs(&o4[r1 + tid + i * THREADS], w);
    }
}

extern "C" void kernel_launch(void* const* d_in, const int* in_sizes, int n_in,
                              void* d_out, int out_size)
{
    const float* a = (const float*)d_in[0];
    const float* b = (const float*)d_in[1];
    float* out = (float*)d_out;

    const int rows = in_sizes[0] / L;               // 8192
    outer_product_rowscale2<<<rows / 2, THREADS>>>(a, b, out);
}

// round 8
// speedup vs baseline: 1.0421x; 1.0421x over previous
#include <cuda_runtime.h>

// out[n, i] = b[n, i] * sum_j a[n, j],  B = L = 8192, fp32.
// Best-known shape (R1): fused, one CTA per row, 256 threads, 8 float4/thread,
// PLAIN cached loads/stores (no .cs hints — every .cs variant measured slower).
// Single refinement vs R1: one-barrier reduction (no serial tid0 chain).

constexpr int L = 8192;
constexpr int THREADS = 256;
constexpr int NWARPS = THREADS / 32;            // 8
constexpr int VECS_PER_ROW = L / 4;             // 2048 float4
constexpr int VPT = VECS_PER_ROW / THREADS;     // 8 per thread

__global__ __launch_bounds__(THREADS, 8)
void outer_product_rowscale(const float* __restrict__ a,
                            const float* __restrict__ b,
                            float* __restrict__ out)
{
    __shared__ float warp_sums[NWARPS];

    const int row = blockIdx.x;
    const int tid = threadIdx.x;

    const float4* a4 = reinterpret_cast<const float4*>(a) + (size_t)row * VECS_PER_ROW;
    const float4* b4 = reinterpret_cast<const float4*>(b) + (size_t)row * VECS_PER_ROW;
    float4* o4       = reinterpret_cast<float4*>(out)     + (size_t)row * VECS_PER_ROW;

    // ---- Phase 1: row-sum of a (coalesced, plain cached) ----
    float s0 = 0.f, s1 = 0.f, s2 = 0.f, s3 = 0.f;
    #pragma unroll
    for (int i = 0; i < VPT; i++) {
        float4 v = a4[tid + i * THREADS];
        s0 += v.x; s1 += v.y; s2 += v.z; s3 += v.w;
    }
    float s = (s0 + s1) + (s2 + s3);

    // warp reduce (xor: full sum in every lane)
    #pragma unroll
    for (int off = 16; off > 0; off >>= 1)
        s += __shfl_xor_sync(0xFFFFFFFFu, s, off);

    if ((tid & 31) == 0) warp_sums[tid >> 5] = s;
    __syncthreads();                             // single barrier

    // Every thread sums the 8 partials (broadcast LDS.128, conflict-free).
    const float4 w0 = *reinterpret_cast<const float4*>(&warp_sums[0]);
    const float4 w1 = *reinterpret_cast<const float4*>(&warp_sums[4]);
    const float scale = ((w0.x + w0.y) + (w0.z + w0.w))
                      + ((w1.x + w1.y) + (w1.z + w1.w));

    // ---- Phase 2: out = b * scale (coalesced, plain cached) ----
    #pragma unroll
    for (int i = 0; i < VPT; i++) {
        float4 v = b4[tid + i * THREADS];
        v.x *= scale; v.y *= scale; v.z *= scale; v.w *= scale;
        o4[tid + i * THREADS] = v;
    }
}

extern "C" void kernel_launch(void* const* d_in, const int* in_sizes, int n_in,
                              void* d_out, int out_size)
{
    const float* a = (const float*)d_in[0];
    const float* b = (const float*)d_in[1];
    float* out = (float*)d_out;

    const int rows = in_sizes[0] / L;            // 8192
    outer_product_rowscale<<<rows, THREADS>>>(a, b, out);
}